// round 14
// baseline (speedup 1.0000x reference)
#include <cuda_runtime.h>
#include <cuda_fp16.h>
#include <math.h>

#define NB   4
#define NC   256
#define NHW  4096
#define NM   (NB*NHW)
#define NGRP 8
#define CPG  32
#define EPSV 1e-5f
#define BM   128
#define BN   128
#define NITER (NHW/BN)

// scratch (allowed: __device__ globals)
static __device__ __half  g_tokh[(size_t)NM*NC];
static __device__ __half  g_qkvh[(size_t)NM*3*NC];
static __device__ __half  g_qkvwh[3*NC*NC];
static __device__ __half  g_projwh[NC*NC];
static __device__ float   g_part[NB*NGRP*8*2];
static __device__ float   g_mean[NB*NGRP];
static __device__ float   g_rstd[NB*NGRP];

// ---------------- PTX helpers ----------------
__device__ __forceinline__ void mma_h(float* c, const unsigned* a, unsigned b0, unsigned b1) {
    asm volatile("mma.sync.aligned.m16n8k16.row.col.f32.f16.f16.f32 "
                 "{%0,%1,%2,%3}, {%4,%5,%6,%7}, {%8,%9}, {%0,%1,%2,%3};\n"
                 : "+f"(c[0]), "+f"(c[1]), "+f"(c[2]), "+f"(c[3])
                 : "r"(a[0]), "r"(a[1]), "r"(a[2]), "r"(a[3]), "r"(b0), "r"(b1));
}
__device__ __forceinline__ void ldsm4(unsigned* r, unsigned addr) {
    asm volatile("ldmatrix.sync.aligned.m8n8.x4.shared.b16 {%0,%1,%2,%3}, [%4];"
                 : "=r"(r[0]), "=r"(r[1]), "=r"(r[2]), "=r"(r[3]) : "r"(addr));
}
__device__ __forceinline__ void ldsm4t(unsigned* r, unsigned addr) {
    asm volatile("ldmatrix.sync.aligned.m8n8.x4.trans.shared.b16 {%0,%1,%2,%3}, [%4];"
                 : "=r"(r[0]), "=r"(r[1]), "=r"(r[2]), "=r"(r[3]) : "r"(addr));
}
__device__ __forceinline__ void cpa16(unsigned s, const void* g) {
    asm volatile("cp.async.cg.shared.global [%0], [%1], 16;" :: "r"(s), "l"(g));
}
#define CP_COMMIT asm volatile("cp.async.commit_group;")
#define CP_WAIT(N) asm volatile("cp.async.wait_group %0;" :: "n"(N))

// swizzles: flip 16B-chunk bits [4:7) with row&7
#define SWZ(row, colb)  ((unsigned)((row)*512 + ((colb) ^ (((row)&7)<<4))))   // 512B rows (Q/K/V/W)
#define SWZP(row, colb) ((unsigned)((row)*256 + ((colb) ^ (((row)&7)<<4))))   // 256B rows (P / transpose)
#define SWZ128(row, colb) ((unsigned)((row)*128 + ((colb) ^ (((row)&7)<<4)))) // 128B rows

// ---------------- GroupNorm statistics: partial (256 CTAs) ----------------
__global__ void gn_stats_part(const float* __restrict__ x) {
    int bg = blockIdx.x >> 3, part = blockIdx.x & 7;
    const float4* p = (const float4*)(x + (size_t)bg * CPG * NHW + (size_t)part * 4 * NHW);
    float s = 0.f, s2 = 0.f;
    #pragma unroll 4
    for (int i = threadIdx.x; i < 4096; i += 256) {
        float4 v = p[i];
        s  += v.x + v.y + v.z + v.w;
        s2 += v.x*v.x + v.y*v.y + v.z*v.z + v.w*v.w;
    }
    __shared__ float shs[8], shq[8];
    int lane = threadIdx.x & 31, wid = threadIdx.x >> 5;
    #pragma unroll
    for (int o = 16; o; o >>= 1) {
        s  += __shfl_down_sync(0xffffffffu, s,  o);
        s2 += __shfl_down_sync(0xffffffffu, s2, o);
    }
    if (lane == 0) { shs[wid] = s; shq[wid] = s2; }
    __syncthreads();
    if (wid == 0 && lane == 0) {
        float ts = 0.f, tq = 0.f;
        #pragma unroll
        for (int i = 0; i < 8; i++) { ts += shs[i]; tq += shq[i]; }
        g_part[(bg*8 + part)*2]     = ts;
        g_part[(bg*8 + part)*2 + 1] = tq;
    }
}
// ---------------- GroupNorm statistics: combine (1 CTA) ----------------
__global__ void gn_stats_final() {
    int t = threadIdx.x;
    if (t < NB*NGRP) {
        float s = 0.f, s2 = 0.f;
        #pragma unroll
        for (int i = 0; i < 8; i++) {
            s  += g_part[(t*8 + i)*2];
            s2 += g_part[(t*8 + i)*2 + 1];
        }
        const float inv = 1.f / (float)(CPG * NHW);
        float mean = s * inv;
        float var  = s2 * inv - mean * mean;
        g_mean[t] = mean;
        g_rstd[t] = rsqrtf(var + EPSV);
    }
}

// ---------------- GroupNorm apply + transpose -> fp16 tokens ----------------
__global__ void gn_apply(const float* __restrict__ x, const float* __restrict__ w,
                         const float* __restrict__ bias) {
    __shared__ float tile[32][33];
    int n0 = blockIdx.x * 32, c0 = blockIdx.y * 32, b = blockIdx.z;
    int tx = threadIdx.x, ty = threadIdx.y;
    #pragma unroll
    for (int cc = ty; cc < 32; cc += 8) {
        int c = c0 + cc;
        int g = c >> 5;
        float rs = g_rstd[b*NGRP + g];
        float al = rs * w[c];
        float be = bias[c] - g_mean[b*NGRP + g] * al;
        tile[cc][tx] = x[((size_t)b*NC + c)*NHW + n0 + tx] * al + be;
    }
    __syncthreads();
    #pragma unroll
    for (int nn = ty; nn < 32; nn += 8) {
        g_tokh[((size_t)(b*NHW + n0 + nn))*NC + c0 + tx] = __float2half(tile[tx][nn]);
    }
}

// ---------------- weight conversion ----------------
__global__ void conv_w(const float* __restrict__ qw, const float* __restrict__ pw) {
    int i = blockIdx.x * blockDim.x + threadIdx.x;
    if (i < 3*NC*NC) g_qkvwh[i] = __float2half(qw[i]);
    int j = i - 3*NC*NC;
    if (j >= 0 && j < NC*NC) g_projwh[j] = __float2half(pw[j]);
}

// ---------------- QKV fp16 NT GEMM, cp.async double-buffered ----------------
__global__ void __launch_bounds__(256) gemm_qkv_h(const float* __restrict__ bias) {
    __shared__ __align__(16) __half Sab[4*128*64];
    const __half* A = g_tokh;
    const __half* B = g_qkvwh;
    int m0 = blockIdx.y * 128, n0 = blockIdx.x * 128;
    int t = threadIdx.x, lane = t & 31, wid = t >> 5;
    int wm = wid >> 2, wn = wid & 3;
    int g = lane >> 2, tig = lane & 3;
    float acc[4][4][4];
    #pragma unroll
    for (int i = 0; i < 4; i++)
        #pragma unroll
        for (int j = 0; j < 4; j++)
            #pragma unroll
            for (int r = 0; r < 4; r++) acc[i][j][r] = 0.f;
    unsigned uA = (unsigned)__cvta_generic_to_shared(Sab);
    unsigned uB = uA + 2*128*64*2;

    #define QKV_LOAD(s, kb) do { \
        unsigned offs = (unsigned)(s)*128*64*2; \
        for (int c = t; c < 128*8; c += 256) { \
            int row = c >> 3, colb = (c & 7) << 4; \
            cpa16(uA + offs + SWZ128(row, colb), A + (size_t)(m0+row)*NC + (kb) + (colb>>1)); \
            cpa16(uB + offs + SWZ128(row, colb), B + (size_t)(n0+row)*NC + (kb) + (colb>>1)); \
        } CP_COMMIT; } while (0)

    QKV_LOAD(0, 0);
    #pragma unroll
    for (int i = 0; i < 4; i++) {
        if (i < 3) { QKV_LOAD((i+1)&1, (i+1)*64); CP_WAIT(1); }
        else CP_WAIT(0);
        __syncthreads();
        unsigned offs = (unsigned)(i&1)*128*64*2;
        #pragma unroll
        for (int kk = 0; kk < 4; kk++) {
            unsigned a[4][4];
            #pragma unroll
            for (int mf = 0; mf < 4; mf++) {
                int row = wm*64 + mf*16 + (lane&15);
                int colb = (kk*16 + (lane>>4)*8)*2;
                ldsm4(a[mf], uA + offs + SWZ128(row, colb));
            }
            #pragma unroll
            for (int p = 0; p < 2; p++) {
                unsigned bb[4];
                int row = wn*32 + p*16 + ((lane>>4)&1)*8 + (lane&7);
                int colb = (kk*16 + ((lane>>3)&1)*8)*2;
                ldsm4(bb, uB + offs + SWZ128(row, colb));
                #pragma unroll
                for (int mf = 0; mf < 4; mf++) {
                    mma_h(acc[mf][2*p],   a[mf], bb[0], bb[1]);
                    mma_h(acc[mf][2*p+1], a[mf], bb[2], bb[3]);
                }
            }
        }
        __syncthreads();
    }
    #pragma unroll
    for (int mf = 0; mf < 4; mf++)
        #pragma unroll
        for (int nf = 0; nf < 4; nf++) {
            int m = m0 + wm*64 + mf*16 + g;
            int n = n0 + wn*32 + nf*8 + 2*tig;
            float b0 = bias[n], b1 = bias[n+1];
            *(__half2*)&g_qkvh[(size_t)m*(3*NC) + n] =
                __floats2half2_rn(acc[mf][nf][0]+b0, acc[mf][nf][1]+b1);
            *(__half2*)&g_qkvh[(size_t)(m+8)*(3*NC) + n] =
                __floats2half2_rn(acc[mf][nf][2]+b0, acc[mf][nf][3]+b1);
        }
}

// ---------------- fused flash attention + proj + residual ----------------
#define OFF_Q   0            // 128x256 fp16 = 65536 (later: O tile, then transpose buf)
#define OFF_K   65536        // 128x256 = 65536 (later: W_proj 256x256 = 128KB spans K+V)
#define OFF_V   131072       // 128x256 = 65536
#define OFF_P   196608       // 128x128 fp16 = 32768
#define OFF_RED 229376       // 256 floats
#define FL_SMEM 230400

__global__ void __launch_bounds__(256, 1) flash_h(
    float* __restrict__ out, const float* __restrict__ pbias, const float* __restrict__ x)
{
    extern __shared__ __align__(16) char smem[];
    __half* Ps = (__half*)(smem + OFF_P);
    __half* Qs = (__half*)(smem + OFF_Q);
    float* s_red = (float*)(smem + OFF_RED);

    const int b = blockIdx.y, m0 = blockIdx.x * BM;
    const int t = threadIdx.x, lane = t & 31, wid = t >> 5;
    const int wm = wid >> 1, wn = wid & 1;            // S phase: 4 x 2
    const int wmp = wid >> 2, wnp = wid & 3;          // PV/proj phase: 2 x 4
    const int g = lane >> 2, tig = lane & 3;

    const __half* Qg = g_qkvh + (size_t)(b*NHW + m0) * (3*NC);
    const __half* Kg = g_qkvh + (size_t)(b*NHW) * (3*NC) + NC;
    const __half* Vg = g_qkvh + (size_t)(b*NHW) * (3*NC) + 2*NC;

    unsigned uS = (unsigned)__cvta_generic_to_shared(smem);
    unsigned uQ = uS + OFF_Q, uK = uS + OFF_K, uV = uS + OFF_V, uP = uS + OFF_P;

    #define LOAD_K(it) do { const __half* kp = Kg + (size_t)(it)*BN*(3*NC); \
        for (int c = t; c < BN*32; c += 256) { \
            int row = c >> 5, colb = (c & 31) << 4; \
            cpa16(uK + SWZ(row, colb), kp + (size_t)row*(3*NC) + (colb>>1)); } } while (0)
    #define LOAD_V(it) do { const __half* vp = Vg + (size_t)(it)*BN*(3*NC); \
        for (int c = t; c < BN*32; c += 256) { \
            int row = c >> 5, colb = (c & 31) << 4; \
            cpa16(uV + SWZ(row, colb), vp + (size_t)row*(3*NC) + (colb>>1)); } } while (0)

    // prologue: G0 = {Q, K0}; G1 = {V0}
    for (int c = t; c < BM*32; c += 256) {
        int row = c >> 5, colb = (c & 31) << 4;
        cpa16(uQ + SWZ(row, colb), Qg + (size_t)row*(3*NC) + (colb>>1));
    }
    LOAD_K(0); CP_COMMIT;
    LOAD_V(0); CP_COMMIT;
    CP_WAIT(1);
    __syncthreads();

    float acc_o[4][8][4];           // 64 rows x 64 cols per warp (PV layout)
    #pragma unroll
    for (int mf = 0; mf < 4; mf++)
        #pragma unroll
        for (int f = 0; f < 8; f++)
            #pragma unroll
            for (int r = 0; r < 4; r++) acc_o[mf][f][r] = 0.f;
    float l0[2] = {0.f, 0.f}, l1[2] = {0.f, 0.f};
    const float C = 0.090169944f;   // log2(e)/16

    for (int i = 0; i < NITER; i++) {
        // ---- S = Q K^T (fp32 acc), warp 32 rows x 64 k ----
        float acc_s[2][8][4];
        #pragma unroll
        for (int mf = 0; mf < 2; mf++)
            #pragma unroll
            for (int f = 0; f < 8; f++)
                #pragma unroll
                for (int r = 0; r < 4; r++) acc_s[mf][f][r] = 0.f;
        #pragma unroll
        for (int d0 = 0; d0 < NC; d0 += 16) {
            unsigned a[2][4];
            #pragma unroll
            for (int mf = 0; mf < 2; mf++) {
                int row = wm*32 + mf*16 + (lane&15);
                int colb = (d0 + (lane>>4)*8)*2;
                ldsm4(a[mf], uQ + SWZ(row, colb));
            }
            #pragma unroll
            for (int q = 0; q < 4; q++) {
                unsigned bb[4];
                int row = wn*64 + q*16 + ((lane>>4)&1)*8 + (lane&7);
                int colb = (d0 + ((lane>>3)&1)*8)*2;
                ldsm4(bb, uK + SWZ(row, colb));
                #pragma unroll
                for (int mf = 0; mf < 2; mf++) {
                    mma_h(acc_s[mf][2*q],   a[mf], bb[0], bb[1]);
                    mma_h(acc_s[mf][2*q+1], a[mf], bb[2], bb[3]);
                }
            }
        }
        // ---- P = exp2(S*C), accumulate l, store P ----
        #pragma unroll
        for (int mf = 0; mf < 2; mf++) {
            int r0 = wm*32 + mf*16 + g;
            #pragma unroll
            for (int f = 0; f < 8; f++) {
                __half2 p01 = h2exp2(__floats2half2_rn(acc_s[mf][f][0]*C, acc_s[mf][f][1]*C));
                __half2 p23 = h2exp2(__floats2half2_rn(acc_s[mf][f][2]*C, acc_s[mf][f][3]*C));
                float2 f01 = __half22float2(p01);
                float2 f23 = __half22float2(p23);
                l0[mf] += f01.x + f01.y;
                l1[mf] += f23.x + f23.y;
                int colb = (wn*64 + f*8 + 2*tig)*2;
                *(__half2*)&Ps[SWZP(r0, colb) >> 1]   = p01;
                *(__half2*)&Ps[SWZP(r0+8, colb) >> 1] = p23;
            }
        }
        __syncthreads();               // K fully consumed, P visible
        if (i < NITER-1) LOAD_K(i+1);
        CP_COMMIT;
        CP_WAIT(1);                    // V(i) arrived
        // ---- O += P V (warp 64 rows x 64 cols, k = all 128) ----
        #pragma unroll
        for (int k0 = 0; k0 < BN; k0 += 16) {
            unsigned a[4][4];
            #pragma unroll
            for (int mf = 0; mf < 4; mf++) {
                int row = wmp*64 + mf*16 + (lane&15);
                int colb = (k0 + (lane>>4)*8)*2;
                ldsm4(a[mf], uP + SWZP(row, colb));
            }
            #pragma unroll
            for (int q = 0; q < 4; q++) {
                unsigned bb[4];
                int row = k0 + ((lane>>3)&1)*8 + (lane&7);
                int colb = (wnp*64 + q*16 + ((lane>>4)&1)*8)*2;
                ldsm4t(bb, uV + SWZ(row, colb));
                #pragma unroll
                for (int mf = 0; mf < 4; mf++) {
                    mma_h(acc_o[mf][2*q],   a[mf], bb[0], bb[1]);
                    mma_h(acc_o[mf][2*q+1], a[mf], bb[2], bb[3]);
                }
            }
        }
        __syncthreads();               // V fully consumed
        if (i < NITER-1) LOAD_V(i+1);
        CP_COMMIT;
        CP_WAIT(1);
    }
    // ---- l reduction (S layout) ----
    #pragma unroll
    for (int mf = 0; mf < 2; mf++) {
        l0[mf] += __shfl_xor_sync(0xffffffffu, l0[mf], 1);
        l0[mf] += __shfl_xor_sync(0xffffffffu, l0[mf], 2);
        l1[mf] += __shfl_xor_sync(0xffffffffu, l1[mf], 1);
        l1[mf] += __shfl_xor_sync(0xffffffffu, l1[mf], 2);
        if (tig == 0) {
            s_red[wn*128 + wm*32 + mf*16 + g]     = l0[mf];
            s_red[wn*128 + wm*32 + mf*16 + g + 8] = l1[mf];
        }
    }
    __syncthreads();                   // s_red ready; all Q/K/V reads done

    // ---- start W_proj load into K+V region (256 rows x 512B = 128KB) ----
    for (int c = t; c < 256*32; c += 256) {
        int row = c >> 5, colb = (c & 31) << 4;
        cpa16(uK + SWZ(row, colb), g_projwh + (size_t)row*NC + (colb>>1));
    }
    CP_COMMIT;

    // ---- write O/l into uQ as [token][c] fp16 (SWZ 512B rows) ----
    #pragma unroll
    for (int mf = 0; mf < 4; mf++) {
        int r0 = wmp*64 + mf*16 + g;
        float il0 = 1.f / (s_red[r0]   + s_red[128 + r0]);
        float il1 = 1.f / (s_red[r0+8] + s_red[128 + r0+8]);
        #pragma unroll
        for (int nf = 0; nf < 8; nf++) {
            int colb = (wnp*64 + nf*8 + 2*tig)*2;
            *(__half2*)&Qs[SWZ(r0, colb) >> 1] =
                __floats2half2_rn(acc_o[mf][nf][0]*il0, acc_o[mf][nf][1]*il0);
            *(__half2*)&Qs[SWZ(r0+8, colb) >> 1] =
                __floats2half2_rn(acc_o[mf][nf][2]*il1, acc_o[mf][nf][3]*il1);
        }
    }
    CP_WAIT(0);
    __syncthreads();                   // O + W visible

    // ---- proj GEMM: [128 tok][256 c] @ W[256 o][256 c]^T, warp 64x64 ----
    float acc_p[4][8][4];
    #pragma unroll
    for (int mf = 0; mf < 4; mf++)
        #pragma unroll
        for (int f = 0; f < 8; f++)
            #pragma unroll
            for (int r = 0; r < 4; r++) acc_p[mf][f][r] = 0.f;
    #pragma unroll
    for (int d0 = 0; d0 < NC; d0 += 16) {
        unsigned a[4][4];
        #pragma unroll
        for (int mf = 0; mf < 4; mf++) {
            int row = wmp*64 + mf*16 + (lane&15);
            int colb = (d0 + (lane>>4)*8)*2;
            ldsm4(a[mf], uQ + SWZ(row, colb));
        }
        #pragma unroll
        for (int q = 0; q < 4; q++) {
            unsigned bb[4];
            int row = wnp*64 + q*16 + ((lane>>4)&1)*8 + (lane&7);
            int colb = (d0 + ((lane>>3)&1)*8)*2;
            ldsm4(bb, uK + SWZ(row, colb));
            #pragma unroll
            for (int mf = 0; mf < 4; mf++) {
                mma_h(acc_p[mf][2*q],   a[mf], bb[0], bb[1]);
                mma_h(acc_p[mf][2*q+1], a[mf], bb[2], bb[3]);
            }
        }
    }
    __syncthreads();                   // done reading uQ (A)

    // ---- transpose acc_p into uQ as [o][token] fp16 (SWZP 256B rows) ----
    #pragma unroll
    for (int mf = 0; mf < 4; mf++) {
        int r0 = wmp*64 + mf*16 + g;   // token rows r0, r0+8
        #pragma unroll
        for (int q = 0; q < 4; q++)
            #pragma unroll
            for (int h = 0; h < 2; h++) {
                int o = wnp*64 + q*16 + h*8 + 2*tig;
                const float* f = acc_p[mf][2*q+h];
                Qs[SWZP(o,   r0*2) >> 1]     = __float2half(f[0]);
                Qs[SWZP(o+1, r0*2) >> 1]     = __float2half(f[1]);
                Qs[SWZP(o,   (r0+8)*2) >> 1] = __float2half(f[2]);
                Qs[SWZP(o+1, (r0+8)*2) >> 1] = __float2half(f[3]);
            }
    }
    __syncthreads();

    // ---- out[b][o][m0..m0+127] = x + bias + proj, coalesced ----
    #pragma unroll
    for (int pass = 0; pass < 4; pass++) {
        int o = pass*64 + (t >> 2);
        int tseg = t & 3;
        float bo = pbias[o];
        size_t base = ((size_t)(b*NC + o))*NHW + m0;
        #pragma unroll
        for (int j = 0; j < 8; j++) {
            int tk = (tseg + j*4) * 4;
            float4 xv = *(const float4*)&x[base + tk];
            __half2 h0 = *(__half2*)&Qs[SWZP(o, tk*2) >> 1];
            __half2 h1 = *(__half2*)&Qs[(SWZP(o, tk*2) >> 1) + 2];
            float4 rv;
            rv.x = xv.x + bo + __half2float(h0.x);
            rv.y = xv.y + bo + __half2float(h0.y);
            rv.z = xv.z + bo + __half2float(h1.x);
            rv.w = xv.w + bo + __half2float(h1.y);
            *(float4*)&out[base + tk] = rv;
        }
    }
}

// ---------------- launch ----------------
extern "C" void kernel_launch(void* const* d_in, const int* in_sizes, int n_in,
                              void* d_out, int out_size) {
    const float* x      = (const float*)d_in[0];
    const float* norm_w = (const float*)d_in[1];
    const float* norm_b = (const float*)d_in[2];
    const float* qkv_w  = (const float*)d_in[3];
    const float* qkv_b  = (const float*)d_in[4];
    const float* proj_w = (const float*)d_in[5];
    const float* proj_b = (const float*)d_in[6];
    float* out = (float*)d_out;

    cudaFuncSetAttribute(flash_h, cudaFuncAttributeMaxDynamicSharedMemorySize, FL_SMEM);

    gn_stats_part<<<NB*NGRP*8, 256>>>(x);
    gn_stats_final<<<1, 32>>>();
    conv_w<<<(3*NC*NC + NC*NC)/256, 256>>>(qkv_w, proj_w);
    gn_apply<<<dim3(NHW/32, NC/32, NB), dim3(32, 8)>>>(x, norm_w, norm_b);
    gemm_qkv_h<<<dim3(6, 128), 256>>>(qkv_b);
    flash_h<<<dim3(NHW/BM, NB), 256, FL_SMEM>>>(out, proj_b, x);
}

// round 17
// speedup vs baseline: 1.5430x; 1.5430x over previous
#include <cuda_runtime.h>
#include <cuda_fp16.h>
#include <math.h>

#define NB   4
#define NC   256
#define NHW  4096
#define NM   (NB*NHW)
#define NGRP 8
#define CPG  32
#define EPSV 1e-5f
#define BM   128
#define BN   128
#define NITER (NHW/BN)

// scratch (allowed: __device__ globals)
static __device__ __half  g_tokh[(size_t)NM*NC];
static __device__ __half  g_qkvh[(size_t)NM*3*NC];
static __device__ __half  g_qkvwh[3*NC*NC];
static __device__ __half  g_projwh[NC*NC];
static __device__ float   g_part[NB*NGRP*8*2];
static __device__ float   g_mean[NB*NGRP];
static __device__ float   g_rstd[NB*NGRP];

// ---------------- PTX helpers ----------------
__device__ __forceinline__ void mma_h(float* c, const unsigned* a, unsigned b0, unsigned b1) {
    asm volatile("mma.sync.aligned.m16n8k16.row.col.f32.f16.f16.f32 "
                 "{%0,%1,%2,%3}, {%4,%5,%6,%7}, {%8,%9}, {%0,%1,%2,%3};\n"
                 : "+f"(c[0]), "+f"(c[1]), "+f"(c[2]), "+f"(c[3])
                 : "r"(a[0]), "r"(a[1]), "r"(a[2]), "r"(a[3]), "r"(b0), "r"(b1));
}
__device__ __forceinline__ void ldsm4(unsigned* r, unsigned addr) {
    asm volatile("ldmatrix.sync.aligned.m8n8.x4.shared.b16 {%0,%1,%2,%3}, [%4];"
                 : "=r"(r[0]), "=r"(r[1]), "=r"(r[2]), "=r"(r[3]) : "r"(addr));
}
__device__ __forceinline__ void ldsm4t(unsigned* r, unsigned addr) {
    asm volatile("ldmatrix.sync.aligned.m8n8.x4.trans.shared.b16 {%0,%1,%2,%3}, [%4];"
                 : "=r"(r[0]), "=r"(r[1]), "=r"(r[2]), "=r"(r[3]) : "r"(addr));
}
__device__ __forceinline__ void cpa16(unsigned s, const void* g) {
    asm volatile("cp.async.cg.shared.global [%0], [%1], 16;" :: "r"(s), "l"(g));
}
#define CP_COMMIT asm volatile("cp.async.commit_group;")
#define CP_WAIT(N) asm volatile("cp.async.wait_group %0;" :: "n"(N))

// swizzles: flip 16B-chunk bits [4:7) with row&7
#define SWZ(row, colb)  ((unsigned)((row)*512 + ((colb) ^ (((row)&7)<<4))))   // 512B rows (Q/K/V/W)
#define SWZP(row, colb) ((unsigned)((row)*256 + ((colb) ^ (((row)&7)<<4))))   // 256B rows (P / transpose)
#define SWZ128(row, colb) ((unsigned)((row)*128 + ((colb) ^ (((row)&7)<<4)))) // 128B rows

// ---------------- GroupNorm statistics: partial (256 CTAs) ----------------
__global__ void gn_stats_part(const float* __restrict__ x) {
    int bg = blockIdx.x >> 3, part = blockIdx.x & 7;
    const float4* p = (const float4*)(x + (size_t)bg * CPG * NHW + (size_t)part * 4 * NHW);
    float s = 0.f, s2 = 0.f;
    #pragma unroll 4
    for (int i = threadIdx.x; i < 4096; i += 256) {
        float4 v = p[i];
        s  += v.x + v.y + v.z + v.w;
        s2 += v.x*v.x + v.y*v.y + v.z*v.z + v.w*v.w;
    }
    __shared__ float shs[8], shq[8];
    int lane = threadIdx.x & 31, wid = threadIdx.x >> 5;
    #pragma unroll
    for (int o = 16; o; o >>= 1) {
        s  += __shfl_down_sync(0xffffffffu, s,  o);
        s2 += __shfl_down_sync(0xffffffffu, s2, o);
    }
    if (lane == 0) { shs[wid] = s; shq[wid] = s2; }
    __syncthreads();
    if (wid == 0 && lane == 0) {
        float ts = 0.f, tq = 0.f;
        #pragma unroll
        for (int i = 0; i < 8; i++) { ts += shs[i]; tq += shq[i]; }
        g_part[(bg*8 + part)*2]     = ts;
        g_part[(bg*8 + part)*2 + 1] = tq;
    }
}
// ---------------- GroupNorm statistics: combine (1 CTA) ----------------
__global__ void gn_stats_final() {
    int t = threadIdx.x;
    if (t < NB*NGRP) {
        float s = 0.f, s2 = 0.f;
        #pragma unroll
        for (int i = 0; i < 8; i++) {
            s  += g_part[(t*8 + i)*2];
            s2 += g_part[(t*8 + i)*2 + 1];
        }
        const float inv = 1.f / (float)(CPG * NHW);
        float mean = s * inv;
        float var  = s2 * inv - mean * mean;
        g_mean[t] = mean;
        g_rstd[t] = rsqrtf(var + EPSV);
    }
}

// ---------------- GroupNorm apply + transpose -> fp16 tokens ----------------
__global__ void gn_apply(const float* __restrict__ x, const float* __restrict__ w,
                         const float* __restrict__ bias) {
    __shared__ float tile[32][33];
    int n0 = blockIdx.x * 32, c0 = blockIdx.y * 32, b = blockIdx.z;
    int tx = threadIdx.x, ty = threadIdx.y;
    #pragma unroll
    for (int cc = ty; cc < 32; cc += 8) {
        int c = c0 + cc;
        int g = c >> 5;
        float rs = g_rstd[b*NGRP + g];
        float al = rs * w[c];
        float be = bias[c] - g_mean[b*NGRP + g] * al;
        tile[cc][tx] = x[((size_t)b*NC + c)*NHW + n0 + tx] * al + be;
    }
    __syncthreads();
    #pragma unroll
    for (int nn = ty; nn < 32; nn += 8) {
        g_tokh[((size_t)(b*NHW + n0 + nn))*NC + c0 + tx] = __float2half(tile[tx][nn]);
    }
}

// ---------------- weight conversion ----------------
__global__ void conv_w(const float* __restrict__ qw, const float* __restrict__ pw) {
    int i = blockIdx.x * blockDim.x + threadIdx.x;
    if (i < 3*NC*NC) g_qkvwh[i] = __float2half(qw[i]);
    int j = i - 3*NC*NC;
    if (j >= 0 && j < NC*NC) g_projwh[j] = __float2half(pw[j]);
}

// ---------------- QKV fp16 NT GEMM, cp.async double-buffered ----------------
__global__ void __launch_bounds__(256) gemm_qkv_h(const float* __restrict__ bias) {
    __shared__ __align__(16) __half Sab[4*128*64];
    const __half* A = g_tokh;
    const __half* B = g_qkvwh;
    int m0 = blockIdx.y * 128, n0 = blockIdx.x * 128;
    int t = threadIdx.x, lane = t & 31, wid = t >> 5;
    int wm = wid >> 2, wn = wid & 3;
    int g = lane >> 2, tig = lane & 3;
    float acc[4][4][4];
    #pragma unroll
    for (int i = 0; i < 4; i++)
        #pragma unroll
        for (int j = 0; j < 4; j++)
            #pragma unroll
            for (int r = 0; r < 4; r++) acc[i][j][r] = 0.f;
    unsigned uA = (unsigned)__cvta_generic_to_shared(Sab);
    unsigned uB = uA + 2*128*64*2;

    #define QKV_LOAD(s, kb) do { \
        unsigned offs = (unsigned)(s)*128*64*2; \
        for (int c = t; c < 128*8; c += 256) { \
            int row = c >> 3, colb = (c & 7) << 4; \
            cpa16(uA + offs + SWZ128(row, colb), A + (size_t)(m0+row)*NC + (kb) + (colb>>1)); \
            cpa16(uB + offs + SWZ128(row, colb), B + (size_t)(n0+row)*NC + (kb) + (colb>>1)); \
        } CP_COMMIT; } while (0)

    QKV_LOAD(0, 0);
    #pragma unroll
    for (int i = 0; i < 4; i++) {
        if (i < 3) { QKV_LOAD((i+1)&1, (i+1)*64); CP_WAIT(1); }
        else CP_WAIT(0);
        __syncthreads();
        unsigned offs = (unsigned)(i&1)*128*64*2;
        #pragma unroll
        for (int kk = 0; kk < 4; kk++) {
            unsigned a[4][4];
            #pragma unroll
            for (int mf = 0; mf < 4; mf++) {
                int row = wm*64 + mf*16 + (lane&15);
                int colb = (kk*16 + (lane>>4)*8)*2;
                ldsm4(a[mf], uA + offs + SWZ128(row, colb));
            }
            #pragma unroll
            for (int p = 0; p < 2; p++) {
                unsigned bb[4];
                int row = wn*32 + p*16 + ((lane>>4)&1)*8 + (lane&7);
                int colb = (kk*16 + ((lane>>3)&1)*8)*2;
                ldsm4(bb, uB + offs + SWZ128(row, colb));
                #pragma unroll
                for (int mf = 0; mf < 4; mf++) {
                    mma_h(acc[mf][2*p],   a[mf], bb[0], bb[1]);
                    mma_h(acc[mf][2*p+1], a[mf], bb[2], bb[3]);
                }
            }
        }
        __syncthreads();
    }
    #pragma unroll
    for (int mf = 0; mf < 4; mf++)
        #pragma unroll
        for (int nf = 0; nf < 4; nf++) {
            int m = m0 + wm*64 + mf*16 + g;
            int n = n0 + wn*32 + nf*8 + 2*tig;
            float b0 = bias[n], b1 = bias[n+1];
            *(__half2*)&g_qkvh[(size_t)m*(3*NC) + n] =
                __floats2half2_rn(acc[mf][nf][0]+b0, acc[mf][nf][1]+b1);
            *(__half2*)&g_qkvh[(size_t)(m+8)*(3*NC) + n] =
                __floats2half2_rn(acc[mf][nf][2]+b0, acc[mf][nf][3]+b1);
        }
}

// ---------------- fused flash attention + proj + residual (low-pressure epilogue) ----------------
#define OFF_Q   0            // 128x256 fp16 = 65536 (epilogue: O tile [tok][c])
#define OFF_K   65536        // 64KB (epilogue: W_proj o 0..127)
#define OFF_V   131072       // 64KB (epilogue: W_proj o 128..255)
#define OFF_P   196608       // 32KB (epilogue: proj transpose [o][tok])
#define OFF_RED 229376       // 256 floats
#define FL_SMEM 230400

__global__ void __launch_bounds__(256, 1) flash_h(
    float* __restrict__ out, const float* __restrict__ pbias, const float* __restrict__ x)
{
    extern __shared__ __align__(16) char smem[];
    __half* Ps = (__half*)(smem + OFF_P);
    __half* Qs = (__half*)(smem + OFF_Q);
    float* s_red = (float*)(smem + OFF_RED);

    const int b = blockIdx.y, m0 = blockIdx.x * BM;
    const int t = threadIdx.x, lane = t & 31, wid = t >> 5;
    const int wm = wid >> 1, wn = wid & 1;            // S phase: 4 x 2
    const int wmp = wid >> 2, wnp = wid & 3;          // PV/proj phase: 2 x 4
    const int g = lane >> 2, tig = lane & 3;

    const __half* Qg = g_qkvh + (size_t)(b*NHW + m0) * (3*NC);
    const __half* Kg = g_qkvh + (size_t)(b*NHW) * (3*NC) + NC;
    const __half* Vg = g_qkvh + (size_t)(b*NHW) * (3*NC) + 2*NC;

    unsigned uS = (unsigned)__cvta_generic_to_shared(smem);
    unsigned uQ = uS + OFF_Q, uK = uS + OFF_K, uV = uS + OFF_V, uP = uS + OFF_P;

    #define LOAD_K(it) do { const __half* kp = Kg + (size_t)(it)*BN*(3*NC); \
        for (int c = t; c < BN*32; c += 256) { \
            int row = c >> 5, colb = (c & 31) << 4; \
            cpa16(uK + SWZ(row, colb), kp + (size_t)row*(3*NC) + (colb>>1)); } } while (0)
    #define LOAD_V(it) do { const __half* vp = Vg + (size_t)(it)*BN*(3*NC); \
        for (int c = t; c < BN*32; c += 256) { \
            int row = c >> 5, colb = (c & 31) << 4; \
            cpa16(uV + SWZ(row, colb), vp + (size_t)row*(3*NC) + (colb>>1)); } } while (0)

    // prologue: G0 = {Q, K0}; G1 = {V0}
    for (int c = t; c < BM*32; c += 256) {
        int row = c >> 5, colb = (c & 31) << 4;
        cpa16(uQ + SWZ(row, colb), Qg + (size_t)row*(3*NC) + (colb>>1));
    }
    LOAD_K(0); CP_COMMIT;
    LOAD_V(0); CP_COMMIT;
    CP_WAIT(1);
    __syncthreads();

    float acc_o[4][8][4];           // 64 rows x 64 cols per warp (PV layout)
    #pragma unroll
    for (int mf = 0; mf < 4; mf++)
        #pragma unroll
        for (int f = 0; f < 8; f++)
            #pragma unroll
            for (int r = 0; r < 4; r++) acc_o[mf][f][r] = 0.f;
    float l0[2] = {0.f, 0.f}, l1[2] = {0.f, 0.f};
    const float C = 0.090169944f;   // log2(e)/16

    for (int i = 0; i < NITER; i++) {
        // ---- S = Q K^T (fp32 acc), warp 32 rows x 64 k ----
        float acc_s[2][8][4];
        #pragma unroll
        for (int mf = 0; mf < 2; mf++)
            #pragma unroll
            for (int f = 0; f < 8; f++)
                #pragma unroll
                for (int r = 0; r < 4; r++) acc_s[mf][f][r] = 0.f;
        #pragma unroll
        for (int d0 = 0; d0 < NC; d0 += 16) {
            unsigned a[2][4];
            #pragma unroll
            for (int mf = 0; mf < 2; mf++) {
                int row = wm*32 + mf*16 + (lane&15);
                int colb = (d0 + (lane>>4)*8)*2;
                ldsm4(a[mf], uQ + SWZ(row, colb));
            }
            #pragma unroll
            for (int q = 0; q < 4; q++) {
                unsigned bb[4];
                int row = wn*64 + q*16 + ((lane>>4)&1)*8 + (lane&7);
                int colb = (d0 + ((lane>>3)&1)*8)*2;
                ldsm4(bb, uK + SWZ(row, colb));
                #pragma unroll
                for (int mf = 0; mf < 2; mf++) {
                    mma_h(acc_s[mf][2*q],   a[mf], bb[0], bb[1]);
                    mma_h(acc_s[mf][2*q+1], a[mf], bb[2], bb[3]);
                }
            }
        }
        // ---- P = exp2(S*C), accumulate l, store P ----
        #pragma unroll
        for (int mf = 0; mf < 2; mf++) {
            int r0 = wm*32 + mf*16 + g;
            #pragma unroll
            for (int f = 0; f < 8; f++) {
                __half2 p01 = h2exp2(__floats2half2_rn(acc_s[mf][f][0]*C, acc_s[mf][f][1]*C));
                __half2 p23 = h2exp2(__floats2half2_rn(acc_s[mf][f][2]*C, acc_s[mf][f][3]*C));
                float2 f01 = __half22float2(p01);
                float2 f23 = __half22float2(p23);
                l0[mf] += f01.x + f01.y;
                l1[mf] += f23.x + f23.y;
                int colb = (wn*64 + f*8 + 2*tig)*2;
                *(__half2*)&Ps[SWZP(r0, colb) >> 1]   = p01;
                *(__half2*)&Ps[SWZP(r0+8, colb) >> 1] = p23;
            }
        }
        __syncthreads();               // K fully consumed, P visible
        if (i < NITER-1) LOAD_K(i+1);
        CP_COMMIT;
        CP_WAIT(1);                    // V(i) arrived
        // ---- O += P V (warp 64 rows x 64 cols, k = all 128) ----
        #pragma unroll
        for (int k0 = 0; k0 < BN; k0 += 16) {
            unsigned a[4][4];
            #pragma unroll
            for (int mf = 0; mf < 4; mf++) {
                int row = wmp*64 + mf*16 + (lane&15);
                int colb = (k0 + (lane>>4)*8)*2;
                ldsm4(a[mf], uP + SWZP(row, colb));
            }
            #pragma unroll
            for (int q = 0; q < 4; q++) {
                unsigned bb[4];
                int row = k0 + ((lane>>3)&1)*8 + (lane&7);
                int colb = (wnp*64 + q*16 + ((lane>>4)&1)*8)*2;
                ldsm4t(bb, uV + SWZ(row, colb));
                #pragma unroll
                for (int mf = 0; mf < 4; mf++) {
                    mma_h(acc_o[mf][2*q],   a[mf], bb[0], bb[1]);
                    mma_h(acc_o[mf][2*q+1], a[mf], bb[2], bb[3]);
                }
            }
        }
        __syncthreads();               // V fully consumed
        if (i < NITER-1) LOAD_V(i+1);
        CP_COMMIT;
        CP_WAIT(1);
    }
    // ---- l reduction (S layout) ----
    #pragma unroll
    for (int mf = 0; mf < 2; mf++) {
        l0[mf] += __shfl_xor_sync(0xffffffffu, l0[mf], 1);
        l0[mf] += __shfl_xor_sync(0xffffffffu, l0[mf], 2);
        l1[mf] += __shfl_xor_sync(0xffffffffu, l1[mf], 1);
        l1[mf] += __shfl_xor_sync(0xffffffffu, l1[mf], 2);
        if (tig == 0) {
            s_red[wn*128 + wm*32 + mf*16 + g]     = l0[mf];
            s_red[wn*128 + wm*32 + mf*16 + g + 8] = l1[mf];
        }
    }
    __syncthreads();                   // s_red ready; all Q/K/V reads done

    // ---- prefetch W_proj halves: o 0..127 -> uK, o 128..255 -> uV ----
    for (int c = t; c < 128*32; c += 256) {
        int row = c >> 5, colb = (c & 31) << 4;
        cpa16(uK + SWZ(row, colb), g_projwh + (size_t)row*NC + (colb>>1));
    }
    CP_COMMIT;
    for (int c = t; c < 128*32; c += 256) {
        int row = c >> 5, colb = (c & 31) << 4;
        cpa16(uV + SWZ(row, colb), g_projwh + (size_t)(128+row)*NC + (colb>>1));
    }
    CP_COMMIT;

    // ---- write normalized O into uQ as [token][c] fp16 (acc_o dies here) ----
    #pragma unroll
    for (int mf = 0; mf < 4; mf++) {
        int r0 = wmp*64 + mf*16 + g;
        float il0 = 1.f / (s_red[r0]   + s_red[128 + r0]);
        float il1 = 1.f / (s_red[r0+8] + s_red[128 + r0+8]);
        #pragma unroll
        for (int nf = 0; nf < 8; nf++) {
            int colb = (wnp*64 + nf*8 + 2*tig)*2;
            *(__half2*)&Qs[SWZ(r0, colb) >> 1] =
                __floats2half2_rn(acc_o[mf][nf][0]*il0, acc_o[mf][nf][1]*il0);
            *(__half2*)&Qs[SWZ(r0+8, colb) >> 1] =
                __floats2half2_rn(acc_o[mf][nf][2]*il1, acc_o[mf][nf][3]*il1);
        }
    }
    CP_WAIT(1);                        // W half 0 ready (half 1 in flight)
    __syncthreads();                   // O visible

    // ---- proj in two o-passes of 128 cols (64-reg accumulator) ----
    #pragma unroll 1
    for (int p = 0; p < 2; p++) {
        if (p == 1) CP_WAIT(0);        // W half 1 ready
        unsigned uW = p ? uV : uK;
        float acc_p[4][4][4];
        #pragma unroll
        for (int mf = 0; mf < 4; mf++)
            #pragma unroll
            for (int f = 0; f < 4; f++)
                #pragma unroll
                for (int r = 0; r < 4; r++) acc_p[mf][f][r] = 0.f;
        #pragma unroll
        for (int d0 = 0; d0 < NC; d0 += 16) {
            unsigned a[4][4];
            #pragma unroll
            for (int mf = 0; mf < 4; mf++) {
                int row = wmp*64 + mf*16 + (lane&15);
                int colb = (d0 + (lane>>4)*8)*2;
                ldsm4(a[mf], uQ + SWZ(row, colb));
            }
            #pragma unroll
            for (int q = 0; q < 2; q++) {
                unsigned bb[4];
                int row = wnp*32 + q*16 + ((lane>>4)&1)*8 + (lane&7);
                int colb = (d0 + ((lane>>3)&1)*8)*2;
                ldsm4(bb, uW + SWZ(row, colb));
                #pragma unroll
                for (int mf = 0; mf < 4; mf++) {
                    mma_h(acc_p[mf][2*q],   a[mf], bb[0], bb[1]);
                    mma_h(acc_p[mf][2*q+1], a[mf], bb[2], bb[3]);
                }
            }
        }
        __syncthreads();               // uP free (p0: mainloop done; p1: pass0 stores done)
        // transpose into uP as [o_local 128][token 128] fp16 (SWZP 256B rows)
        #pragma unroll
        for (int mf = 0; mf < 4; mf++) {
            int r0 = wmp*64 + mf*16 + g;
            #pragma unroll
            for (int q = 0; q < 2; q++)
                #pragma unroll
                for (int h = 0; h < 2; h++) {
                    int ol = wnp*32 + q*16 + h*8 + 2*tig;
                    const float* f = acc_p[mf][2*q+h];
                    Ps[SWZP(ol,   r0*2) >> 1]     = __float2half(f[0]);
                    Ps[SWZP(ol+1, r0*2) >> 1]     = __float2half(f[1]);
                    Ps[SWZP(ol,   (r0+8)*2) >> 1] = __float2half(f[2]);
                    Ps[SWZP(ol+1, (r0+8)*2) >> 1] = __float2half(f[3]);
                }
        }
        __syncthreads();
        // coalesced store: out[b][o][m0..m0+127] = x + bias + proj
        #pragma unroll
        for (int sub = 0; sub < 2; sub++) {
            int ol = sub*64 + (t >> 2);
            int o = p*128 + ol;
            int tseg = t & 3;
            float bo = pbias[o];
            size_t base = ((size_t)(b*NC + o))*NHW + m0;
            #pragma unroll
            for (int j = 0; j < 8; j++) {
                int tk = (tseg + j*4) * 4;
                float4 xv = *(const float4*)&x[base + tk];
                unsigned off = SWZP(ol, tk*2) >> 1;
                __half2 h0 = *(__half2*)&Ps[off];
                __half2 h1 = *(__half2*)&Ps[off + 2];
                float4 rv;
                rv.x = xv.x + bo + __half2float(h0.x);
                rv.y = xv.y + bo + __half2float(h0.y);
                rv.z = xv.z + bo + __half2float(h1.x);
                rv.w = xv.w + bo + __half2float(h1.y);
                *(float4*)&out[base + tk] = rv;
            }
        }
    }
}

// ---------------- launch ----------------
extern "C" void kernel_launch(void* const* d_in, const int* in_sizes, int n_in,
                              void* d_out, int out_size) {
    const float* x      = (const float*)d_in[0];
    const float* norm_w = (const float*)d_in[1];
    const float* norm_b = (const float*)d_in[2];
    const float* qkv_w  = (const float*)d_in[3];
    const float* qkv_b  = (const float*)d_in[4];
    const float* proj_w = (const float*)d_in[5];
    const float* proj_b = (const float*)d_in[6];
    float* out = (float*)d_out;

    cudaFuncSetAttribute(flash_h, cudaFuncAttributeMaxDynamicSharedMemorySize, FL_SMEM);

    gn_stats_part<<<NB*NGRP*8, 256>>>(x);
    gn_stats_final<<<1, 32>>>();
    conv_w<<<(3*NC*NC + NC*NC)/256, 256>>>(qkv_w, proj_w);
    gn_apply<<<dim3(NHW/32, NC/32, NB), dim3(32, 8)>>>(x, norm_w, norm_b);
    gemm_qkv_h<<<dim3(6, 128), 256>>>(qkv_b);
    flash_h<<<dim3(NHW/BM, NB), 256, FL_SMEM>>>(out, proj_b, x);
}